// round 11
// baseline (speedup 1.0000x reference)
#include <cuda_runtime.h>
#include <cuda_fp16.h>
#include <cstdint>

// ===========================================================================
// ChebyKANLinear, mma.sync m16n8k16 FP16 (fp32 accumulate).
// R10: KC=128 (16 i/chunk), 2-stage ring (192KB smem). Halves the number of
// chunk barriers to amortize the ~850-cyc/chunk fixed cost seen in R8/R9.
// Mainloop inner s-step body identical to the 414us R9 kernel.
// ===========================================================================

#define BATCH   8192
#define IN_F    1024
#define OUT_F   1024
#define BM      128
#define BN      256
#define KC      128           // 16 i-values * 8 degrees per chunk
#define NCHUNK  64            // IN_F / 16
#define A_BYTES 32768         // BM * KC * 2 (fp16)
#define B_BYTES 65536         // BN * KC * 2 (fp16)
#define STAGE_BYTES (A_BYTES + B_BYTES)
#define NSTG    2
#define NTHR    384
#define CSCALE  4096.0f
#define OSCALE  (1.0f / 4096.0f)

// Static device scratch (no runtime allocation allowed)
__device__ uint32_t g_BF[(size_t)128 * 16 * 2048];    // B fp16 frags, 16 MB
__device__ float g_part[512 * OUT_F];                 // bias partials, 2 MB
__device__ float g_bias[OUT_F];

// ---------------------------------------------------------------- utils
__device__ __forceinline__ uint32_t h2pack(float lo, float hi) {
    __half2 h = __floats2half2_rn(lo, hi);
    return *reinterpret_cast<uint32_t*>(&h);
}

__device__ __forceinline__ float fast_tanh(float x) {
    float e = __expf(2.f * x);
    return 1.f - __fdividef(2.f, e + 1.f);
}

__device__ __forceinline__ void cpa16(uint32_t dst, const void* src) {
    asm volatile("cp.async.cg.shared.global [%0], [%1], 16;\n" :: "r"(dst), "l"(src));
}
__device__ __forceinline__ void cpa_commit() { asm volatile("cp.async.commit_group;\n"); }
template <int N>
__device__ __forceinline__ void cpa_wait() {
    asm volatile("cp.async.wait_group %0;\n" :: "n"(N) : "memory");
}

__device__ __forceinline__ void lds128(uint4& v, uint32_t addr) {
    asm volatile("ld.shared.v4.b32 {%0,%1,%2,%3}, [%4];"
                 : "=r"(v.x), "=r"(v.y), "=r"(v.z), "=r"(v.w) : "r"(addr));
}
__device__ __forceinline__ void sts128(uint32_t addr, uint32_t a, uint32_t b,
                                       uint32_t c, uint32_t d) {
    asm volatile("st.shared.v4.b32 [%0], {%1,%2,%3,%4};"
                 :: "r"(addr), "r"(a), "r"(b), "r"(c), "r"(d));
}

__device__ __forceinline__ void mma16(float* c, const uint4& a, uint32_t b0, uint32_t b1) {
    asm volatile(
        "mma.sync.aligned.m16n8k16.row.col.f32.f16.f16.f32 "
        "{%0,%1,%2,%3},{%4,%5,%6,%7},{%8,%9},{%0,%1,%2,%3};\n"
        : "+f"(c[0]), "+f"(c[1]), "+f"(c[2]), "+f"(c[3])
        : "r"(a.x), "r"(a.y), "r"(a.z), "r"(a.w), "r"(b0), "r"(b1));
}

// A-fragment lane swizzle (conflict-free for gen STS.128 and consumer LDS.128)
__device__ __forceinline__ uint32_t a_lswz(uint32_t lane_c) {
    return (lane_c * 16u) ^ (((lane_c >> 3) & 3u) << 4);
}

// ---------------------------------------------------------------- prologues
// B fragments (fp16, scaled by 2^12) + per-block bias partials.
// Block b handles i-pair (i0, i0+1), i0 = (b>>2)*8 + (b&3)*2. (KC64 slices;
// a KC=128 chunk n concatenates slices c64 = 2n (s 0..3) and 2n+1 (s 4..7).)
__global__ void __launch_bounds__(256) prep_kernel(const float* __restrict__ coef) {
    __shared__ uint32_t stg[8192];     // [wnG16][nip4][lane32][w4]
    const int b = blockIdx.x;
    const int c = b >> 2, s = b & 3;
    const int i0 = c * 8 + s * 2;
    #pragma unroll
    for (int r = 0; r < 4; r++) {
        const int col = threadIdx.x + (r << 8);
        const float* c0 = coef + (size_t)i0 * 9216 + (size_t)col * 9;
        const float* c1 = c0 + 9216;
        float cv0[9], cv1[9];
        #pragma unroll
        for (int d = 0; d < 9; d++) { cv0[d] = __ldg(c0 + d); cv1[d] = __ldg(c1 + d); }
        const int g = col & 7, colpar = (col >> 3) & 1;
        const int nip = (col >> 4) & 3, wnG = col >> 6;
        const int base = wnG * 512 + nip * 128 + colpar * 2;
        #pragma unroll
        for (int t = 0; t < 4; t++) {
            stg[base + (g * 4 + t) * 4 + 0] =
                h2pack(cv0[2 * t + 1] * CSCALE, cv0[2 * t + 2] * CSCALE);
            stg[base + (g * 4 + t) * 4 + 1] =
                h2pack(cv1[2 * t + 1] * CSCALE, cv1[2 * t + 2] * CSCALE);
        }
        g_part[(size_t)b * OUT_F + col] = cv0[0] + cv1[0];   // bias partial
    }
    __syncthreads();
    float4* dst = reinterpret_cast<float4*>(g_BF);
    const float4* src = reinterpret_cast<const float4*>(stg);
    #pragma unroll
    for (int k = 0; k < 8; k++) {
        const int q = threadIdx.x + (k << 8);   // 0..2047
        const int wnG = q >> 7, inner = q & 127;
        dst[(size_t)(c * 16 + wnG) * 512 + s * 128 + inner] = src[q];
    }
}

// bias[o] = sum over 512 partials (deterministic fixed order)
__global__ void __launch_bounds__(256) bias_red_kernel() {
    const int o = (blockIdx.x << 8) + threadIdx.x;
    float s0 = 0.f, s1 = 0.f, s2 = 0.f, s3 = 0.f;
    #pragma unroll 4
    for (int b = 0; b < 512; b += 4) {
        s0 += g_part[(size_t)(b + 0) * OUT_F + o];
        s1 += g_part[(size_t)(b + 1) * OUT_F + o];
        s2 += g_part[(size_t)(b + 2) * OUT_F + o];
        s3 += g_part[(size_t)(b + 3) * OUT_F + o];
    }
    g_bias[o] = (s0 + s1) + (s2 + s3);
}

// ---------------------------------------------------------------- main GEMM
// 384 thr: warps 0-7 consumers (128x256 tile, warp 64x64, m16n8k16),
// warps 8-11 producers (tanh fused). 2-stage ring, 192KB smem.
__global__ void __launch_bounds__(NTHR, 1) cheby_main(const float* __restrict__ X,
                                                      float* __restrict__ Out) {
    extern __shared__ uint8_t sm[];
    const uint32_t smA = (uint32_t)__cvta_generic_to_shared(sm);          // 2 x 32KB
    const uint32_t smB = smA + NSTG * A_BYTES;                            // 2 x 64KB

    const int tid  = threadIdx.x;
    const int lane = tid & 31;
    const int w    = tid >> 5;
    const int bm   = blockIdx.y << 7;
    const int bx   = blockIdx.x;
    const int bn   = bx << 8;

    const float4* bsrc = reinterpret_cast<const float4*>(g_BF);

    if (w < 8) {
        // ======================= CONSUMER (256 threads) =====================
        const int wm = w >> 2;           // 0..1 (64-row block)
        const int wn = w & 3;            // 0..3 (64-col block)
        const int g  = lane >> 2;
        const int t  = lane & 3;
        const uint32_t lsw = a_lswz((uint32_t)lane);

        float acc[4][8][4];
        #pragma unroll
        for (int mi = 0; mi < 4; mi++)
            #pragma unroll
            for (int ni = 0; ni < 8; ni++)
                #pragma unroll
                for (int q = 0; q < 4; q++) acc[mi][ni][q] = 0.f;

        __syncthreads();    // chunk 0 produced

        for (int c = 0; c < NCHUNK; c++) {
            const int st = c & 1;
            // A: [s:8][G:8][512B]; warp rows: G = wm*4+mi
            const uint32_t aBase = smA + (uint32_t)(st * A_BYTES + wm * 2048) + lsw;
            // B: [wnG:4][s:8][nip:4][lane*16]
            const uint32_t bBase = smB + (uint32_t)(st * B_BYTES + wn * 16384 + lane * 16);

            #pragma unroll
            for (int s = 0; s < 8; s++) {
                uint4 aC[4];
                #pragma unroll
                for (int mi = 0; mi < 4; mi++)
                    lds128(aC[mi], aBase + (uint32_t)(s * 4096 + mi * 512));
                uint4 bC[4];
                #pragma unroll
                for (int nip = 0; nip < 4; nip++)
                    lds128(bC[nip], bBase + (uint32_t)(s * 2048 + nip * 512));
                #pragma unroll
                for (int ni = 0; ni < 8; ni++) {
                    const uint32_t b0 = (ni & 1) ? bC[ni >> 1].z : bC[ni >> 1].x;
                    const uint32_t b1 = (ni & 1) ? bC[ni >> 1].w : bC[ni >> 1].y;
                    #pragma unroll
                    for (int mi = 0; mi < 4; mi++)
                        mma16(acc[mi][ni], aC[mi], b0, b1);
                }
            }
            __syncthreads();
        }

        // --- epilogue: out = acc * 2^-12 + bias ---
        #pragma unroll
        for (int ni = 0; ni < 8; ni++) {
            const int cc = bn + (wn << 6) + (ni << 3) + (t << 1);
            const float2 bv = *reinterpret_cast<const float2*>(g_bias + cc);
            #pragma unroll
            for (int mi = 0; mi < 4; mi++) {
                const int r0 = bm + (wm << 6) + (mi << 4) + g;
                float2 o0 = { fmaf(acc[mi][ni][0], OSCALE, bv.x),
                              fmaf(acc[mi][ni][1], OSCALE, bv.y) };
                float2 o1 = { fmaf(acc[mi][ni][2], OSCALE, bv.x),
                              fmaf(acc[mi][ni][3], OSCALE, bv.y) };
                *reinterpret_cast<float2*>(Out + (size_t)r0 * OUT_F + cc)       = o0;
                *reinterpret_cast<float2*>(Out + (size_t)(r0 + 8) * OUT_F + cc) = o1;
            }
        }
    } else {
        // ======================= PRODUCER (128 threads) =====================
        const int ptid = tid - 256;
        // 4 generator units per thread: u = ptid + e*128, u in [0,512)
        // unit u: s = u&7, g = (u>>3)&7, G = u>>6; rows G*16+g, +8;
        // i-pair = 16n + 2s, +1  -> x cols n*16 + 2s, +1

        #define PRODUCE(n)                                                        \
        do {                                                                      \
            const int st_ = (n) & 1;                                              \
            /* B: two KC64 slices h=0,1; 4 wnG blocks of 512 float4 each */       \
            const uint32_t dstB_ = smB + (uint32_t)(st_ * B_BYTES);               \
            _Pragma("unroll")                                                     \
            for (int k = 0; k < 32; k++) {                                        \
                const int blk = k >> 2;          /* 0..7 */                       \
                const int wng = blk >> 1, h = blk & 1;                            \
                const int inner = ptid + ((k & 3) << 7);                          \
                cpa16(dstB_ + (uint32_t)(wng * 16384 + h * 8192 + inner * 16),    \
                      bsrc + (size_t)((((n) * 2 + h) * 16) + (bx << 2) + wng)     \
                                 * 512 + inner);                                  \
            }                                                                     \
            cpa_commit();                                                         \
            /* A generation with fused tanh */                                    \
            const uint32_t aDst_ = smA + (uint32_t)(st_ * A_BYTES);               \
            _Pragma("unroll")                                                     \
            for (int e = 0; e < 4; e++) {                                         \
                const int u = ptid + (e << 7);                                    \
                const int s_ = u & 7, g_ = (u >> 3) & 7, G_ = u >> 6;             \
                const int rA = bm + (G_ << 4) + g_;                               \
                const float2 xA = *reinterpret_cast<const float2*>(               \
                    X + (size_t)rA * IN_F + ((n) << 4) + (s_ << 1));              \
                const float2 xB = *reinterpret_cast<const float2*>(               \
                    X + (size_t)(rA + 8) * IN_F + ((n) << 4) + (s_ << 1));        \
                const float tA0 = fast_tanh(xA.x), tA1 = fast_tanh(xA.y);         \
                const float tB0 = fast_tanh(xB.x), tB1 = fast_tanh(xB.y);         \
                float TA0[8], TA1[8], TB0[8], TB1[8];                             \
                TA0[0] = tA0; TA1[0] = tA1; TB0[0] = tB0; TB1[0] = tB1;           \
                TA0[1] = 2.f * tA0 * tA0 - 1.f;                                   \
                TA1[1] = 2.f * tA1 * tA1 - 1.f;                                   \
                TB0[1] = 2.f * tB0 * tB0 - 1.f;                                   \
                TB1[1] = 2.f * tB1 * tB1 - 1.f;                                   \
                _Pragma("unroll")                                                 \
                for (int d = 2; d < 8; d++) {                                     \
                    TA0[d] = 2.f * tA0 * TA0[d - 1] - TA0[d - 2];                 \
                    TA1[d] = 2.f * tA1 * TA1[d - 1] - TA1[d - 2];                 \
                    TB0[d] = 2.f * tB0 * TB0[d - 1] - TB0[d - 2];                 \
                    TB1[d] = 2.f * tB1 * TB1[d - 1] - TB1[d - 2];                 \
                }                                                                 \
                const uint32_t ab_ = aDst_ + (uint32_t)(s_ * 4096 + G_ * 512);    \
                _Pragma("unroll")                                                 \
                for (int t = 0; t < 4; t++)                                       \
                    sts128(ab_ + a_lswz((uint32_t)(g_ * 4 + t)),                  \
                           h2pack(TA0[2 * t], TA0[2 * t + 1]),                    \
                           h2pack(TB0[2 * t], TB0[2 * t + 1]),                    \
                           h2pack(TA1[2 * t], TA1[2 * t + 1]),                    \
                           h2pack(TB1[2 * t], TB1[2 * t + 1]));                   \
            }                                                                     \
            cpa_wait<0>();                                                        \
        } while (0)

        PRODUCE(0);
        __syncthreads();    // chunk 0 ready

        for (int c = 0; c < NCHUNK; c++) {
            if (c + 1 < NCHUNK) PRODUCE(c + 1);
            __syncthreads();
        }
        #undef PRODUCE
    }
}

// --------------------------------------------------------------------------
extern "C" void kernel_launch(void* const* d_in, const int* in_sizes, int n_in,
                              void* d_out, int out_size) {
    (void)in_sizes; (void)n_in; (void)out_size;
    const float* x    = (const float*)d_in[0];
    const float* coef = (const float*)d_in[1];
    float* out        = (float*)d_out;

    const int smem_bytes = NSTG * STAGE_BYTES;   // 196608
    cudaFuncSetAttribute(cheby_main, cudaFuncAttributeMaxDynamicSharedMemorySize,
                         smem_bytes);

    prep_kernel<<<512, 256>>>(coef);
    bias_red_kernel<<<4, 256>>>();
    cheby_main<<<dim3(OUT_F / BN, BATCH / BM), NTHR, smem_bytes>>>(x, out);
}

// round 12
// speedup vs baseline: 1.0830x; 1.0830x over previous
#include <cuda_runtime.h>
#include <cuda_fp16.h>
#include <cstdint>

// ===========================================================================
// ChebyKANLinear, mma.sync m16n8k16 FP16 (fp32 accumulate).
// R11: R9 dataflow (KC=64) + 4-stage ring + split named barriers:
//   producers bar.arrive(FULL[s]) / bar.sync(FREE[s]);
//   consumers bar.sync(FULL[s]) / bar.arrive(FREE[s]).
// Removes the full 12-warp rendezvous per chunk that paced consumers by
// producer completion (the ~850cyc/chunk residual in R9).
// ===========================================================================

#define BATCH   8192
#define IN_F    1024
#define OUT_F   1024
#define BM      128
#define BN      256
#define KC      64            // 8 i-values * 8 degrees per chunk
#define NCHUNK  128           // IN_F / 8
#define A_BYTES 16384         // BM * KC * 2 (fp16)
#define B_BYTES 32768         // BN * KC * 2 (fp16)
#define STAGE_BYTES (A_BYTES + B_BYTES)
#define NSTG    4
#define NTHR    384
#define CSCALE  4096.0f
#define OSCALE  (1.0f / 4096.0f)

// Static device scratch (no runtime allocation allowed)
__device__ uint32_t g_BF[(size_t)128 * 16 * 2048];    // B fp16 frags, 16 MB
__device__ float g_part[512 * OUT_F];                 // bias partials, 2 MB
__device__ float g_bias[OUT_F];

// ---------------------------------------------------------------- utils
__device__ __forceinline__ uint32_t h2pack(float lo, float hi) {
    __half2 h = __floats2half2_rn(lo, hi);
    return *reinterpret_cast<uint32_t*>(&h);
}

__device__ __forceinline__ float fast_tanh(float x) {
    float e = __expf(2.f * x);
    return 1.f - __fdividef(2.f, e + 1.f);
}

__device__ __forceinline__ void cpa16(uint32_t dst, const void* src) {
    asm volatile("cp.async.cg.shared.global [%0], [%1], 16;\n" :: "r"(dst), "l"(src));
}
__device__ __forceinline__ void cpa_commit() { asm volatile("cp.async.commit_group;\n"); }
template <int N>
__device__ __forceinline__ void cpa_wait() {
    asm volatile("cp.async.wait_group %0;\n" :: "n"(N) : "memory");
}

// Split named barriers, 384 participants each.
// FULL[s]: id 1+s (stage s data ready). FREE[s]: id 5+s (stage s reusable).
__device__ __forceinline__ void bar_sync_id(int id) {
    asm volatile("bar.sync %0, %1;" :: "r"(id), "n"(NTHR) : "memory");
}
__device__ __forceinline__ void bar_arrive_id(int id) {
    asm volatile("bar.arrive %0, %1;" :: "r"(id), "n"(NTHR) : "memory");
}

__device__ __forceinline__ void lds128(uint4& v, uint32_t addr) {
    asm volatile("ld.shared.v4.b32 {%0,%1,%2,%3}, [%4];"
                 : "=r"(v.x), "=r"(v.y), "=r"(v.z), "=r"(v.w) : "r"(addr));
}
__device__ __forceinline__ void sts128(uint32_t addr, uint32_t a, uint32_t b,
                                       uint32_t c, uint32_t d) {
    asm volatile("st.shared.v4.b32 [%0], {%1,%2,%3,%4};"
                 :: "r"(addr), "r"(a), "r"(b), "r"(c), "r"(d));
}

__device__ __forceinline__ void mma16(float* c, const uint4& a, uint32_t b0, uint32_t b1) {
    asm volatile(
        "mma.sync.aligned.m16n8k16.row.col.f32.f16.f16.f32 "
        "{%0,%1,%2,%3},{%4,%5,%6,%7},{%8,%9},{%0,%1,%2,%3};\n"
        : "+f"(c[0]), "+f"(c[1]), "+f"(c[2]), "+f"(c[3])
        : "r"(a.x), "r"(a.y), "r"(a.z), "r"(a.w), "r"(b0), "r"(b1));
}

// A-fragment lane swizzle (conflict-free for gen STS.128 and consumer LDS.128)
__device__ __forceinline__ uint32_t a_lswz(uint32_t lane_c) {
    return (lane_c * 16u) ^ (((lane_c >> 3) & 3u) << 4);
}

// ---------------------------------------------------------------- prologues
// B fragments (fp16, scaled by 2^12) + per-block bias partials.
// Block b handles i-pair (i0, i0+1), i0 = (b>>2)*8 + (b&3)*2.
__global__ void __launch_bounds__(256) prep_kernel(const float* __restrict__ coef) {
    __shared__ uint32_t stg[8192];     // [wnG16][nip4][lane32][w4]
    const int b = blockIdx.x;
    const int c = b >> 2, s = b & 3;
    const int i0 = c * 8 + s * 2;
    #pragma unroll
    for (int r = 0; r < 4; r++) {
        const int col = threadIdx.x + (r << 8);
        const float* c0 = coef + (size_t)i0 * 9216 + (size_t)col * 9;
        const float* c1 = c0 + 9216;
        float cv0[9], cv1[9];
        #pragma unroll
        for (int d = 0; d < 9; d++) { cv0[d] = __ldg(c0 + d); cv1[d] = __ldg(c1 + d); }
        const int g = col & 7, colpar = (col >> 3) & 1;
        const int nip = (col >> 4) & 3, wnG = col >> 6;
        const int base = wnG * 512 + nip * 128 + colpar * 2;
        #pragma unroll
        for (int t = 0; t < 4; t++) {
            stg[base + (g * 4 + t) * 4 + 0] =
                h2pack(cv0[2 * t + 1] * CSCALE, cv0[2 * t + 2] * CSCALE);
            stg[base + (g * 4 + t) * 4 + 1] =
                h2pack(cv1[2 * t + 1] * CSCALE, cv1[2 * t + 2] * CSCALE);
        }
        g_part[(size_t)b * OUT_F + col] = cv0[0] + cv1[0];   // bias partial
    }
    __syncthreads();
    float4* dst = reinterpret_cast<float4*>(g_BF);
    const float4* src = reinterpret_cast<const float4*>(stg);
    #pragma unroll
    for (int k = 0; k < 8; k++) {
        const int q = threadIdx.x + (k << 8);   // 0..2047
        const int wnG = q >> 7, inner = q & 127;
        dst[(size_t)(c * 16 + wnG) * 512 + s * 128 + inner] = src[q];
    }
}

// bias[o] = sum over 512 partials (deterministic fixed order)
__global__ void __launch_bounds__(256) bias_red_kernel() {
    const int o = (blockIdx.x << 8) + threadIdx.x;
    float s0 = 0.f, s1 = 0.f, s2 = 0.f, s3 = 0.f;
    #pragma unroll 4
    for (int b = 0; b < 512; b += 4) {
        s0 += g_part[(size_t)(b + 0) * OUT_F + o];
        s1 += g_part[(size_t)(b + 1) * OUT_F + o];
        s2 += g_part[(size_t)(b + 2) * OUT_F + o];
        s3 += g_part[(size_t)(b + 3) * OUT_F + o];
    }
    g_bias[o] = (s0 + s1) + (s2 + s3);
}

// ---------------------------------------------------------------- main GEMM
// 384 thr: warps 0-7 consumers (128x256 tile, warp 64x64, m16n8k16),
// warps 8-11 producers (tanh fused). 4-stage ring = 192KB smem.
__global__ void __launch_bounds__(NTHR, 1) cheby_main(const float* __restrict__ X,
                                                      float* __restrict__ Out) {
    extern __shared__ uint8_t sm[];
    const uint32_t smA = (uint32_t)__cvta_generic_to_shared(sm);          // 4 x 16KB
    const uint32_t smB = smA + NSTG * A_BYTES;                            // 4 x 32KB

    const int tid  = threadIdx.x;
    const int lane = tid & 31;
    const int w    = tid >> 5;
    const int bm   = blockIdx.y << 7;
    const int bx   = blockIdx.x;
    const int bn   = bx << 8;

    const float4* bsrc = reinterpret_cast<const float4*>(g_BF);

    if (w < 8) {
        // ======================= CONSUMER (256 threads) =====================
        const int wm = w >> 2;           // 0..1 (64-row block)
        const int wn = w & 3;            // 0..3 (64-col block)
        const int g  = lane >> 2;
        const int t  = lane & 3;
        const uint32_t lsw = a_lswz((uint32_t)lane);

        float acc[4][8][4];
        #pragma unroll
        for (int mi = 0; mi < 4; mi++)
            #pragma unroll
            for (int ni = 0; ni < 8; ni++)
                #pragma unroll
                for (int q = 0; q < 4; q++) acc[mi][ni][q] = 0.f;

        for (int c = 0; c < NCHUNK; c++) {
            const int st = c & 3;
            bar_sync_id(1 + st);                 // wait stage FULL
            const uint32_t aBase = smA + (uint32_t)(st * A_BYTES + wm * 2048) + lsw;
            const uint32_t bBase = smB + (uint32_t)(st * B_BYTES + wn * 8192 + lane * 16);

            #pragma unroll
            for (int s = 0; s < 4; s++) {
                uint4 aC[4];
                #pragma unroll
                for (int mi = 0; mi < 4; mi++)
                    lds128(aC[mi], aBase + (uint32_t)(s * 4096 + mi * 512));
                uint4 bC[4];
                #pragma unroll
                for (int nip = 0; nip < 4; nip++)
                    lds128(bC[nip], bBase + (uint32_t)(s * 2048 + nip * 512));
                #pragma unroll
                for (int ni = 0; ni < 8; ni++) {
                    const uint32_t b0 = (ni & 1) ? bC[ni >> 1].z : bC[ni >> 1].x;
                    const uint32_t b1 = (ni & 1) ? bC[ni >> 1].w : bC[ni >> 1].y;
                    #pragma unroll
                    for (int mi = 0; mi < 4; mi++)
                        mma16(acc[mi][ni], aC[mi], b0, b1);
                }
            }
            bar_arrive_id(5 + st);               // stage FREE
        }

        // --- epilogue: out = acc * 2^-12 + bias ---
        #pragma unroll
        for (int ni = 0; ni < 8; ni++) {
            const int cc = bn + (wn << 6) + (ni << 3) + (t << 1);
            const float2 bv = *reinterpret_cast<const float2*>(g_bias + cc);
            #pragma unroll
            for (int mi = 0; mi < 4; mi++) {
                const int r0 = bm + (wm << 6) + (mi << 4) + g;
                float2 o0 = { fmaf(acc[mi][ni][0], OSCALE, bv.x),
                              fmaf(acc[mi][ni][1], OSCALE, bv.y) };
                float2 o1 = { fmaf(acc[mi][ni][2], OSCALE, bv.x),
                              fmaf(acc[mi][ni][3], OSCALE, bv.y) };
                *reinterpret_cast<float2*>(Out + (size_t)r0 * OUT_F + cc)       = o0;
                *reinterpret_cast<float2*>(Out + (size_t)(r0 + 8) * OUT_F + cc) = o1;
            }
        }
    } else {
        // ======================= PRODUCER (128 threads) =====================
        const int ptid = tid - 256;
        // 2 generator units per thread: u = ptid, ptid+128
        // unit u: s = u&3, g = (u>>2)&7, G = u>>5; rows G*16+g, +8; i = 8c+2s,+1

        #define PRODUCE(n)                                                        \
        do {                                                                      \
            const int st_ = (n) & 3;                                              \
            /* B: 4 wnG blocks of 512 float4 */                                   \
            const uint32_t dstB_ = smB + (uint32_t)(st_ * B_BYTES);               \
            _Pragma("unroll")                                                     \
            for (int k = 0; k < 16; k++) {                                        \
                const int wng = k >> 2;                                           \
                const int inner = ptid + ((k & 3) << 7);                          \
                cpa16(dstB_ + (uint32_t)(wng * 8192 + inner * 16),                \
                      bsrc + (size_t)((n) * 16 + (bx << 2) + wng) * 512 + inner); \
            }                                                                     \
            cpa_commit();                                                         \
            /* A generation with fused tanh */                                    \
            const uint32_t aDst_ = smA + (uint32_t)(st_ * A_BYTES);               \
            _Pragma("unroll")                                                     \
            for (int e = 0; e < 2; e++) {                                         \
                const int u = ptid + (e << 7);                                    \
                const int s_ = u & 3, g_ = (u >> 2) & 7, G_ = u >> 5;             \
                const int rA = bm + (G_ << 4) + g_;                               \
                const float2 xA = *reinterpret_cast<const float2*>(               \
                    X + (size_t)rA * IN_F + ((n) << 3) + (s_ << 1));              \
                const float2 xB = *reinterpret_cast<const float2*>(               \
                    X + (size_t)(rA + 8) * IN_F + ((n) << 3) + (s_ << 1));        \
                const float tA0 = fast_tanh(xA.x), tA1 = fast_tanh(xA.y);         \
                const float tB0 = fast_tanh(xB.x), tB1 = fast_tanh(xB.y);         \
                float TA0[8], TA1[8], TB0[8], TB1[8];                             \
                TA0[0] = tA0; TA1[0] = tA1; TB0[0] = tB0; TB1[0] = tB1;           \
                TA0[1] = 2.f * tA0 * tA0 - 1.f;                                   \
                TA1[1] = 2.f * tA1 * tA1 - 1.f;                                   \
                TB0[1] = 2.f * tB0 * tB0 - 1.f;                                   \
                TB1[1] = 2.f * tB1 * tB1 - 1.f;                                   \
                _Pragma("unroll")                                                 \
                for (int d = 2; d < 8; d++) {                                     \
                    TA0[d] = 2.f * tA0 * TA0[d - 1] - TA0[d - 2];                 \
                    TA1[d] = 2.f * tA1 * TA1[d - 1] - TA1[d - 2];                 \
                    TB0[d] = 2.f * tB0 * TB0[d - 1] - TB0[d - 2];                 \
                    TB1[d] = 2.f * tB1 * TB1[d - 1] - TB1[d - 2];                 \
                }                                                                 \
                const uint32_t ab_ = aDst_ + (uint32_t)(s_ * 4096 + G_ * 512);    \
                _Pragma("unroll")                                                 \
                for (int t = 0; t < 4; t++)                                       \
                    sts128(ab_ + a_lswz((uint32_t)(g_ * 4 + t)),                  \
                           h2pack(TA0[2 * t], TA0[2 * t + 1]),                    \
                           h2pack(TB0[2 * t], TB0[2 * t + 1]),                    \
                           h2pack(TA1[2 * t], TA1[2 * t + 1]),                    \
                           h2pack(TB1[2 * t], TB1[2 * t + 1]));                   \
            }                                                                     \
        } while (0)

        // n=0: no FREE wait, no arrive yet
        PRODUCE(0);
        for (int n = 1; n < NCHUNK; n++) {
            if (n >= NSTG) bar_sync_id(5 + (n & 3));   // wait stage FREE
            PRODUCE(n);
            cpa_wait<1>();                              // group n-1 drained
            bar_arrive_id(1 + ((n - 1) & 3));           // stage n-1 FULL
        }
        cpa_wait<0>();                                  // last group drained
        bar_arrive_id(1 + ((NCHUNK - 1) & 3));          // last stage FULL
        #undef PRODUCE
    }
}

// --------------------------------------------------------------------------
extern "C" void kernel_launch(void* const* d_in, const int* in_sizes, int n_in,
                              void* d_out, int out_size) {
    (void)in_sizes; (void)n_in; (void)out_size;
    const float* x    = (const float*)d_in[0];
    const float* coef = (const float*)d_in[1];
    float* out        = (float*)d_out;

    const int smem_bytes = NSTG * STAGE_BYTES;   // 196608
    cudaFuncSetAttribute(cheby_main, cudaFuncAttributeMaxDynamicSharedMemorySize,
                         smem_bytes);

    prep_kernel<<<512, 256>>>(coef);
    bias_red_kernel<<<4, 256>>>();
    cheby_main<<<dim3(OUT_F / BN, BATCH / BM), NTHR, smem_bytes>>>(x, out);
}